// round 1
// baseline (speedup 1.0000x reference)
#include <cuda_runtime.h>

#define NN 50000
#define NE 600000
#define HH 128
#define LL 6

typedef unsigned long long u64;

// ---------------- scratch (static device buffers; no allocation) ----------------
__device__ float g_h  [NN*HH];
__device__ float g_hn [NN*HH];
__device__ float g_up [NN*HH];
__device__ float g_agg[NN*HH];
__device__ float g_m1 [(size_t)NE*HH];
__device__ float g_tail[NE*4];
__device__ float g_deg[NN];
__device__ float g_invdeg[NN];
__device__ float g_var[NN];
__device__ float g_sum[HH];
__device__ float g_sumsq[HH];
__device__ float g_ba[HH];
__device__ float g_bc[HH];

// ---------------- packed f32x2 helpers (Blackwell FFMA2) ----------------
__device__ __forceinline__ void fma2(u64 &d, u64 a, u64 b){
    asm("fma.rn.f32x2 %0, %1, %2, %0;" : "+l"(d) : "l"(a), "l"(b));
}
__device__ __forceinline__ u64 pk2(float x, float y){
    u64 r; asm("mov.b64 %0, {%1, %2};" : "=l"(r) : "f"(x), "f"(y)); return r;
}
__device__ __forceinline__ float2 upk2(u64 v){
    float2 r; asm("mov.b64 {%0, %1}, %2;" : "=f"(r.x), "=f"(r.y) : "l"(v)); return r;
}

#define EPI_RELU_STORE 0
#define EPI_ATOMIC     1
#define EPI_RESID      2
#define EPI_STORE      3

// AMODE: 0 = A is dense rows x 128
//        1 = message gather: [h[dst] | h[src] | tail(du,dpx,dpy,var_i)]  K=260
//        2 = update gather:  [h[n] | agg[n]/deg[n] | var[n]]            K=257
template<int AMODE, int EPI>
__global__ __launch_bounds__(256)
void gemm_k(const float* __restrict__ A, const float* __restrict__ W,
            const float* __restrict__ bias, float* __restrict__ out,
            const int* __restrict__ esrc, const int* __restrict__ edst,
            int rows, int K)
{
    __shared__ float As[16][68];     // [k][m], padded stride vs bank conflicts
    __shared__ float Bs[16][128];    // [k][j]
    __shared__ int   s_ia[64];
    __shared__ int   s_ib[64];
    __shared__ float s_fa[64];
    __shared__ float s_fb[64];

    const int tid  = threadIdx.x;
    const int base = blockIdx.x * 64;

    if (tid < 64) {
        int r = base + tid; if (r >= rows) r = rows - 1;
        if (AMODE == 1)        { s_ia[tid] = edst[r]; s_ib[tid] = esrc[r]; }
        else if (AMODE == 2)   { s_fa[tid] = g_invdeg[r]; s_fb[tid] = g_var[r]; }
        if (EPI == EPI_ATOMIC) { s_ia[tid] = edst[r]; }
    }
    __syncthreads();

    const int lm  = tid >> 2;         // A tile row 0..63
    const int lc  = (tid & 3) * 4;    // A tile k offset 0/4/8/12
    const int bk  = tid >> 5;         // B tile k row 0..7
    const int bj  = (tid & 31) * 4;   // B tile col
    const int ty  = tid >> 5;         // output row group 0..7
    const int txc = (tid & 31) * 4;   // output cols

    int arow = base + lm; if (arow >= rows) arow = rows - 1;

    u64 acc[4][4];
    #pragma unroll
    for (int i=0;i<4;i++)
        #pragma unroll
        for (int j=0;j<4;j++) acc[i][j]=0ULL;

    const int nkt = (K + 15) >> 4;
    for (int kt = 0; kt < nkt; kt++) {
        // ---- gather A fragment (one float4 per thread) ----
        float4 av = make_float4(0.f,0.f,0.f,0.f);
        int k0 = kt*16 + lc;
        if (AMODE == 0) {
            av = *(const float4*)&A[arow*128 + k0];
        } else if (AMODE == 1) {
            if (k0 < 128)       av = *(const float4*)&g_h[s_ia[lm]*HH + k0];
            else if (k0 < 256)  av = *(const float4*)&g_h[s_ib[lm]*HH + (k0-128)];
            else if (k0 == 256) av = *(const float4*)&g_tail[arow*4];
        } else {
            if (k0 < 128)       av = *(const float4*)&g_h[arow*HH + k0];
            else if (k0 < 256)  { av = *(const float4*)&g_agg[arow*HH + (k0-128)];
                                  float s = s_fa[lm];
                                  av.x*=s; av.y*=s; av.z*=s; av.w*=s; }
            else if (k0 == 256) av = make_float4(s_fb[lm],0.f,0.f,0.f);
        }
        // ---- B fragment (two float4 per thread) ----
        float4 bv0 = make_float4(0.f,0.f,0.f,0.f), bv1 = bv0;
        int kg0 = kt*16 + bk, kg1 = kg0 + 8;
        if (kg0 < K) bv0 = *(const float4*)&W[kg0*128 + bj];
        if (kg1 < K) bv1 = *(const float4*)&W[kg1*128 + bj];

        // previous compute finished at loop-bottom sync
        As[lc+0][lm]=av.x; As[lc+1][lm]=av.y; As[lc+2][lm]=av.z; As[lc+3][lm]=av.w;
        *(float4*)&Bs[bk  ][bj] = bv0;
        *(float4*)&Bs[bk+8][bj] = bv1;
        __syncthreads();

        #pragma unroll
        for (int k=0;k<16;k++){
            union { float4 f; u64 u[2]; } ua0, ua1, ub;
            ua0.f = *(const float4*)&As[k][ty*8];
            ua1.f = *(const float4*)&As[k][ty*8+4];
            ub.f  = *(const float4*)&Bs[k][txc];
            u64 ap[4] = { ua0.u[0], ua0.u[1], ua1.u[0], ua1.u[1] };  // row pairs, packed for free
            u64 bp[4] = { pk2(ub.f.x,ub.f.x), pk2(ub.f.y,ub.f.y),
                          pk2(ub.f.z,ub.f.z), pk2(ub.f.w,ub.f.w) };
            #pragma unroll
            for (int i=0;i<4;i++)
                #pragma unroll
                for (int j=0;j<4;j++)
                    fma2(acc[i][j], ap[i], bp[j]);
        }
        __syncthreads();
    }

    // ---- epilogue ----
    float4 bb = *(const float4*)&bias[txc];
    #pragma unroll
    for (int i=0;i<4;i++){
        float2 c0 = upk2(acc[i][0]);
        float2 c1 = upk2(acc[i][1]);
        float2 c2 = upk2(acc[i][2]);
        float2 c3 = upk2(acc[i][3]);
        #pragma unroll
        for (int sub=0; sub<2; sub++){
            int lrow = ty*8 + i*2 + sub;
            int r = base + lrow;
            if (r >= rows) continue;
            float v0 = (sub? c0.y : c0.x) + bb.x;
            float v1 = (sub? c1.y : c1.x) + bb.y;
            float v2 = (sub? c2.y : c2.x) + bb.z;
            float v3 = (sub? c3.y : c3.x) + bb.w;
            if (EPI != EPI_STORE){
                v0=fmaxf(v0,0.f); v1=fmaxf(v1,0.f); v2=fmaxf(v2,0.f); v3=fmaxf(v3,0.f);
            }
            if (EPI == EPI_ATOMIC){
                int n = s_ia[lrow];
                atomicAdd(&out[n*HH+txc+0], v0);
                atomicAdd(&out[n*HH+txc+1], v1);
                atomicAdd(&out[n*HH+txc+2], v2);
                atomicAdd(&out[n*HH+txc+3], v3);
            } else if (EPI == EPI_RESID){
                float4 hv = *(const float4*)&g_h[r*HH+txc];
                *(float4*)&out[r*HH+txc] =
                    make_float4(hv.x+v0, hv.y+v1, hv.z+v2, hv.w+v3);
            } else {
                *(float4*)&out[r*HH+txc] = make_float4(v0,v1,v2,v3);
            }
        }
    }
}

// ---------------- small kernels ----------------
__global__ void k_zero(float* __restrict__ p, int n){
    int i = blockIdx.x*blockDim.x + threadIdx.x;
    if (i < n) p[i] = 0.f;
}

__global__ void k_node_pre(const float* __restrict__ pos){
    int n = blockIdx.x*blockDim.x + threadIdx.x;
    if (n < NN){ g_var[n] = pos[n*3+0]; g_deg[n] = 0.f; }
}

__global__ void k_edge_pre(const float* __restrict__ u, const float* __restrict__ pos,
                           const int* __restrict__ src, const int* __restrict__ dst){
    int e = blockIdx.x*blockDim.x + threadIdx.x;
    if (e < NE){
        int s = src[e], d = dst[e];
        g_tail[e*4+0] = u[d] - u[s];
        g_tail[e*4+1] = pos[d*3+1] - pos[s*3+1];
        g_tail[e*4+2] = pos[d*3+2] - pos[s*3+2];
        g_tail[e*4+3] = pos[d*3+0];
        atomicAdd(&g_deg[d], 1.f);
    }
}

__global__ void k_invdeg(){
    int n = blockIdx.x*blockDim.x + threadIdx.x;
    if (n < NN) g_invdeg[n] = 1.f / fmaxf(g_deg[n], 1.f);
}

__global__ void k_h0(const float* __restrict__ u, const float* __restrict__ pos,
                     const float* __restrict__ W1, const float* __restrict__ b1){
    int idx = blockIdx.x*blockDim.x + threadIdx.x;
    if (idx < NN*HH){
        int n = idx >> 7, j = idx & 127;
        float val = u[n]        * W1[j]
                  + pos[n*3+1]  * W1[128+j]
                  + pos[n*3+2]  * W1[256+j]
                  + pos[n*3+0]  * W1[384+j]
                  + b1[j];
        g_hn[idx] = val;
    }
}

__global__ void k_bn_zero(){
    int t = threadIdx.x;
    if (t < HH){ g_sum[t]=0.f; g_sumsq[t]=0.f; }
}

__global__ void k_bn_stats(const float* __restrict__ x){
    int j = threadIdx.x;
    int r0 = blockIdx.x * 256;
    int rend = min(r0 + 256, NN);
    float s = 0.f, s2 = 0.f;
    for (int r = r0; r < rend; r++){
        float v = x[r*HH + j];
        s += v; s2 += v*v;
    }
    atomicAdd(&g_sum[j], s);
    atomicAdd(&g_sumsq[j], s2);
}

__global__ void k_bn_fin(const float* __restrict__ g, const float* __restrict__ be){
    int j = threadIdx.x;
    float mu  = g_sum[j]   * (1.f/NN);
    float var = g_sumsq[j] * (1.f/NN) - mu*mu;
    float a = g[j] * rsqrtf(var + 1e-5f);
    g_ba[j] = a;
    g_bc[j] = be[j] - a*mu;
}

template<bool RELU>
__global__ void k_bn_apply(const float* __restrict__ x, float* __restrict__ y){
    int i4 = blockIdx.x*blockDim.x + threadIdx.x;
    if (i4 < NN*HH/4){
        int j = (i4*4) & 127;
        float4 v = *(const float4*)&x[i4*4];
        float4 a = *(const float4*)&g_ba[j];
        float4 c = *(const float4*)&g_bc[j];
        float4 o = make_float4(a.x*v.x+c.x, a.y*v.y+c.y, a.z*v.z+c.z, a.w*v.w+c.w);
        if (RELU){
            o.x=fmaxf(o.x,0.f); o.y=fmaxf(o.y,0.f);
            o.z=fmaxf(o.z,0.f); o.w=fmaxf(o.w,0.f);
        }
        *(float4*)&y[i4*4] = o;
    }
}

// ---------------- CNN head: per-node tiny convs ----------------
__global__ __launch_bounds__(64)
void k_cnn(const float* __restrict__ c1W, const float* __restrict__ c1b,
           const float* __restrict__ c2W, const float* __restrict__ c2b,
           const float* __restrict__ c3W, const float* __restrict__ c3b,
           float* __restrict__ out){
    __shared__ float sx[64][129];
    __shared__ float w1[64], w2[384], w3[64], b1[4], b2[8], b3[1];
    int tid = threadIdx.x;
    int base = blockIdx.x * 64;

    w1[tid] = c1W[tid];
    w3[tid] = c3W[tid];
    for (int i = tid; i < 384; i += 64) w2[i] = c2W[i];
    if (tid < 4) b1[tid] = c1b[tid];
    if (tid < 8) b2[tid] = c2b[tid];
    if (tid == 0) b3[0] = c3b[0];

    for (int r = 0; r < 64; r++){
        int row = base + r; int rr = row < NN ? row : NN-1;
        sx[r][tid]    = g_h[rr*HH + tid];
        sx[r][tid+64] = g_h[rr*HH + tid + 64];
    }
    __syncthreads();

    int node = base + tid;
    if (node >= NN) return;

    float o1[4][38];
    #pragma unroll
    for (int c = 0; c < 4; c++)
        for (int p = 0; p < 38; p++){
            float s = b1[c];
            #pragma unroll
            for (int k = 0; k < 16; k++) s += sx[tid][3*p+k] * w1[c*16+k];
            o1[c][p] = fmaxf(s, 0.f);
        }
    float o2[8][9];
    for (int o = 0; o < 8; o++)
        for (int q = 0; q < 9; q++){
            float s = b2[o];
            for (int c = 0; c < 4; c++)
                #pragma unroll
                for (int k = 0; k < 12; k++) s += o1[c][3*q+k] * w2[(o*4+c)*12+k];
            o2[o][q] = fmaxf(s, 0.f);
        }
    float s = b3[0];
    #pragma unroll
    for (int o = 0; o < 8; o++)
        #pragma unroll
        for (int k = 0; k < 8; k++) s += o2[o][k] * w3[o*8+k];

    out[node] = 0.001f * s;   // dt = cumsum(DT*0.1) with TW=1
}

// ---------------- launch ----------------
extern "C" void kernel_launch(void* const* d_in, const int* in_sizes, int n_in,
                              void* d_out, int out_size)
{
    const float* u      = (const float*)d_in[0];
    const float* pos    = (const float*)d_in[1];
    const int*   ei     = (const int*)  d_in[2];
    const int*   src    = ei;
    const int*   dst    = ei + NE;
    const float* emb_W1 = (const float*)d_in[3];
    const float* emb_b1 = (const float*)d_in[4];
    const float* emb_g1 = (const float*)d_in[5];
    const float* emb_be1= (const float*)d_in[6];
    const float* emb_W2 = (const float*)d_in[7];
    const float* emb_b2 = (const float*)d_in[8];
    const float* emb_g2 = (const float*)d_in[9];
    const float* emb_be2= (const float*)d_in[10];
    const float* m1W    = (const float*)d_in[11];
    const float* m1b    = (const float*)d_in[12];
    const float* m2W    = (const float*)d_in[13];
    const float* m2b    = (const float*)d_in[14];
    const float* u1W    = (const float*)d_in[15];
    const float* u1b    = (const float*)d_in[16];
    const float* u2W    = (const float*)d_in[17];
    const float* u2b    = (const float*)d_in[18];
    const float* bng    = (const float*)d_in[19];
    const float* bnb    = (const float*)d_in[20];
    const float* c1W    = (const float*)d_in[21];
    const float* c1b    = (const float*)d_in[22];
    const float* c2W    = (const float*)d_in[23];
    const float* c2b    = (const float*)d_in[24];
    const float* c3W    = (const float*)d_in[25];
    const float* c3b    = (const float*)d_in[26];
    float* out = (float*)d_out;

    float *p_h, *p_hn, *p_up, *p_agg, *p_m1;
    cudaGetSymbolAddress((void**)&p_h,   g_h);
    cudaGetSymbolAddress((void**)&p_hn,  g_hn);
    cudaGetSymbolAddress((void**)&p_up,  g_up);
    cudaGetSymbolAddress((void**)&p_agg, g_agg);
    cudaGetSymbolAddress((void**)&p_m1,  g_m1);

    const int GN  = (NN + 63) / 64;      // node-row GEMM blocks
    const int GE  = NE / 64;             // edge-row GEMM blocks (exact)
    const int ELT = (NN*HH + 255) / 256;

    auto bn = [&](const float* x, float* y, const float* g, const float* be, bool relu){
        k_bn_zero<<<1,128>>>();
        k_bn_stats<<<(NN+255)/256,128>>>(x);
        k_bn_fin<<<1,128>>>(g, be);
        if (relu) k_bn_apply<true ><<<(NN*HH/4+255)/256,256>>>(x, y);
        else      k_bn_apply<false><<<(NN*HH/4+255)/256,256>>>(x, y);
    };

    // preprocessing
    k_node_pre<<<(NN+255)/256,256>>>(pos);
    k_edge_pre<<<(NE+255)/256,256>>>(u, pos, src, dst);
    k_invdeg<<<(NN+255)/256,256>>>();

    // embedding
    k_h0<<<(NN*HH+255)/256,256>>>(u, pos, emb_W1, emb_b1);
    bn(p_hn, p_h, emb_g1, emb_be1, true);
    gemm_k<0,EPI_STORE><<<GN,256>>>(p_h, emb_W2, emb_b2, p_hn,
                                    nullptr, nullptr, NN, 128);
    bn(p_hn, p_h, emb_g2, emb_be2, false);

    // message-passing layers
    for (int i = 0; i < LL; i++){
        gemm_k<1,EPI_RELU_STORE><<<GE,256>>>(nullptr, m1W + (size_t)i*260*128,
                                             m1b + i*128, p_m1, src, dst, NE, 260);
        k_zero<<<ELT,256>>>(p_agg, NN*HH);
        gemm_k<0,EPI_ATOMIC><<<GE,256>>>(p_m1, m2W + (size_t)i*128*128,
                                         m2b + i*128, p_agg, nullptr, dst, NE, 128);
        gemm_k<2,EPI_RELU_STORE><<<GN,256>>>(nullptr, u1W + (size_t)i*257*128,
                                             u1b + i*128, p_up, nullptr, nullptr, NN, 257);
        gemm_k<0,EPI_RESID><<<GN,256>>>(p_up, u2W + (size_t)i*128*128,
                                        u2b + i*128, p_hn, nullptr, nullptr, NN, 128);
        bn(p_hn, p_h, bng + i*128, bnb + i*128, false);
    }

    // CNN head
    k_cnn<<<GN,64>>>(c1W, c1b, c2W, c2b, c3W, c3b, out);
}